// round 15
// baseline (speedup 1.0000x reference)
#include <cuda_runtime.h>

// LocSE fused kernel for GB300.
// Shapes (fixed): B=4, N=16384, DIMS=2, K1=17, UNITS=128, CH=53.
// Factorization: the (17 x 53) @ (53 x 64) per-neighborhood matmul
// = one shared 34-dim projection S[u] + a rank-3 per-j term.
// R15: R11 (7 CTAs/SM, group-of-4 gather MLP, pts read once per j) with
// DEFAULT (.wb) stores on the out tensor instead of .cs — single-variable
// A/B of the streaming-store hint against the observed 5.2-5.3 TB/s write wall.

#define NPTS   16384
#define BN     65536          // B*N
#define K1V    17
#define WARPS  8
#define OUT_FLOATS_PER_G 2176 // 17*128

__global__ __launch_bounds__(256, 7)
void locse_kernel(const float2* __restrict__ pc,      // (B,N) float2
                  const float2* __restrict__ feats,   // (B,N,32) float2 (64 floats)
                  const int*    __restrict__ nidx,    // (B,N,17)
                  const float*  __restrict__ W,       // (53,64)
                  const float*  __restrict__ bvec,    // (64,)
                  float2*       __restrict__ out,     // (B,N,17,64) float2
                  float2*       __restrict__ ggf)     // (B,N,1,2) as float2
{
    // sW4[i*32 + lane] = ( W[2+3i][2l], W[2+3i][2l+1], W[3+3i][2l], W[3+3i][2l+1] )
    __shared__ float4 sW4[K1V * 32];
    __shared__ float  sWx[64], sWy[64], sWn[64], sB[64];
    __shared__ float4 pts[WARPS][K1V];   // (x, y, norm, (ii*32)_as_float)

    const int tid = threadIdx.x;

    // ---- stage derived weights (once per block) ----
    if (tid < 64) {
        const int u = tid;
        float wx = W[u];          // W[0][u]
        float wy = W[64 + u];     // W[1][u]
        float wn = 0.f;
        #pragma unroll
        for (int i = 0; i < K1V; i++) {
            wx -= W[(2 + 3 * i) * 64 + u];
            wy -= W[(3 + 3 * i) * 64 + u];
            wn += W[(4 + 3 * i) * 64 + u];
        }
        sWx[u] = wx; sWy[u] = wy; sWn[u] = wn; sB[u] = bvec[u];
    }
    {
        float* sW4F = (float*)sW4;
        #pragma unroll 1
        for (int t = tid; t < K1V * 128; t += 256) {
            const int i = t >> 7;            // point index
            const int l = (t >> 2) & 31;     // lane
            const int c = t & 3;             // component
            const int row = (c < 2 ? 2 : 3) + 3 * i;
            const int col = 2 * l + (c & 1);
            sW4F[t] = W[row * 64 + col];
        }
    }
    __syncthreads();

    const int lane = tid & 31, warp = tid >> 5;
    const unsigned g = blockIdx.x * WARPS + warp;   // neighborhood id in [0, BN)
    const unsigned b = g >> 14;                     // g / 16384
    const int* __restrict__ ip = nidx + (size_t)g * K1V;

    // ---- phase A: gather 17 points, norms; stash feats offset (ii*32) ----
    float x = 0.f, y = 0.f;
    if (lane < K1V) {
        const int ii = ip[lane];
        const float2 p = pc[(size_t)b * NPTS + ii];
        x = p.x; y = p.y;
        const float nrm = sqrtf(x * x + y * y);
        pts[warp][lane] = make_float4(x, y, nrm, __int_as_float(ii * 32));
    }
    __syncwarp();

    // ---- ggf: two-pass centered stats over 17 points (matches reference) ----
    float sx = x, sy = y;
    #pragma unroll
    for (int o = 16; o; o >>= 1) {
        sx += __shfl_xor_sync(0xffffffffu, sx, o);
        sy += __shfl_xor_sync(0xffffffffu, sy, o);
    }
    const float inv17 = 1.0f / 17.0f;
    const float mx = sx * inv17, my = sy * inv17;
    const float xc = (lane < K1V) ? (x - mx) : 0.f;
    const float yc = (lane < K1V) ? (y - my) : 0.f;
    float sxx = xc * xc, syy = yc * yc, sxy = xc * yc;
    #pragma unroll
    for (int o = 16; o; o >>= 1) {
        sxx += __shfl_xor_sync(0xffffffffu, sxx, o);
        syy += __shfl_xor_sync(0xffffffffu, syy, o);
        sxy += __shfl_xor_sync(0xffffffffu, sxy, o);
    }
    if (lane == 0) {
        const float vx = sxx * inv17, vy = syy * inv17, cov = sxy * inv17;
        const float m    = cov / (vx + 1e-8f);
        const float pear = cov / (sqrtf(vx * vy) + 1e-8f);
        __stcs(ggf + g, make_float2(m, 1.0f - pear));
    }

    // ---- phase B: shared projection S[u]; one LDS.128 (pt) + one LDS.128 (w) per i ----
    float acc0 = sB[2 * lane], acc1 = sB[2 * lane + 1];
    #pragma unroll
    for (int i = 0; i < K1V; i++) {
        const float4 pt = pts[warp][i];                  // LDS broadcast
        const float4 w  = sW4[i * 32 + lane];
        acc0 = fmaf(pt.x, w.x, acc0);
        acc1 = fmaf(pt.x, w.y, acc1);
        acc0 = fmaf(pt.y, w.z, acc0);
        acc1 = fmaf(pt.y, w.w, acc1);
    }
    const float wx0 = sWx[2 * lane], wx1 = sWx[2 * lane + 1];
    const float wy0 = sWy[2 * lane], wy1 = sWy[2 * lane + 1];
    const float wn0 = sWn[2 * lane], wn1 = sWn[2 * lane + 1];

    // ---- phase C: group-of-4 gather MLP; pts read exactly once per j ----
    float2* __restrict__ outBase = out + (size_t)g * (OUT_FLOATS_PER_G / 2) + lane;
    const float2* __restrict__ fb = feats + (size_t)b * NPTS * 32 + lane;

    #define CST(j, pt, fv) do {                                               \
        float r0 = fmaf((pt).z, wn0, fmaf((pt).y, wy0, fmaf((pt).x, wx0, acc0))); \
        float r1 = fmaf((pt).z, wn1, fmaf((pt).y, wy1, fmaf((pt).x, wx1, acc1))); \
        r0 = fmaxf(r0, 0.f); r1 = fmaxf(r1, 0.f);                             \
        float2* row = outBase + (j) * 64;                                     \
        row[0]  = (fv);                      /* default .wb store */          \
        row[32] = make_float2(r0, r1);       /* default .wb store */          \
    } while (0)

    #pragma unroll 1
    for (int j = 0; j < 16; j += 4) {
        // read the 4 pts ONCE into registers
        const float4 p0 = pts[warp][j];
        const float4 p1 = pts[warp][j + 1];
        const float4 p2 = pts[warp][j + 2];
        const float4 p3 = pts[warp][j + 3];
        // 4 independent gathers in flight
        const float2 q0 = fb[__float_as_int(p0.w)];
        const float2 q1 = fb[__float_as_int(p1.w)];
        const float2 q2 = fb[__float_as_int(p2.w)];
        const float2 q3 = fb[__float_as_int(p3.w)];
        CST(j + 0, p0, q0);
        CST(j + 1, p1, q1);
        CST(j + 2, p2, q2);
        CST(j + 3, p3, q3);
    }
    {
        const float4 p = pts[warp][16];
        const float2 q = fb[__float_as_int(p.w)];
        CST(16, p, q);
    }
    #undef CST
}

extern "C" void kernel_launch(void* const* d_in, const int* in_sizes, int n_in,
                              void* d_out, int out_size) {
    const float2* pc    = (const float2*)d_in[0];
    const float2* feats = (const float2*)d_in[1];
    const int*    nidx  = (const int*)d_in[2];
    const float*  W     = (const float*)d_in[3];
    const float*  bvec  = (const float*)d_in[4];

    float* out = (float*)d_out;
    // ggf tensor is concatenated after the main output
    float2* ggf = (float2*)(out + (size_t)BN * OUT_FLOATS_PER_G);

    locse_kernel<<<BN / WARPS, 256>>>(pc, feats, nidx, W, bvec,
                                      (float2*)out, ggf);
}

// round 16
// speedup vs baseline: 1.0781x; 1.0781x over previous
#include <cuda_runtime.h>

// LocSE fused kernel for GB300 — FINAL (R11 configuration, re-benched).
// Shapes (fixed): B=4, N=16384, DIMS=2, K1=17, UNITS=128, CH=53.
//
// Design summary (evidence-backed, 13 rounds):
//  * Algebraic factorization: the per-neighborhood (17x53)@(53x64) MLP
//    decomposes into one shared 34-dim projection S[u] (over the 17 points)
//    plus a rank-3 per-j term (x,y,norm) — 10.6x FLOP reduction, making the
//    kernel purely HBM-write-bound (573 MB compulsory output).
//  * 7 CTAs/SM x 256 thr (32 regs, 56 warps/SM) — occupancy beyond this flat.
//  * Group-of-4 gather MLP in phase C, pts read exactly ONCE per j (extra LDS
//    traffic proven harmful in R9), feats reads default-cached (L2-resident).
//  * .cs streaming stores (beat .wb by 8%); 2x STG.64 per row per lane.
// Measured wall: DRAM ~5.3 TB/s = HBM3e effective write-stream ceiling.

#define NPTS   16384
#define BN     65536          // B*N
#define K1V    17
#define WARPS  8
#define OUT_FLOATS_PER_G 2176 // 17*128

__global__ __launch_bounds__(256, 7)
void locse_kernel(const float2* __restrict__ pc,      // (B,N) float2
                  const float2* __restrict__ feats,   // (B,N,32) float2 (64 floats)
                  const int*    __restrict__ nidx,    // (B,N,17)
                  const float*  __restrict__ W,       // (53,64)
                  const float*  __restrict__ bvec,    // (64,)
                  float2*       __restrict__ out,     // (B,N,17,64) float2
                  float2*       __restrict__ ggf)     // (B,N,1,2) as float2
{
    // sW4[i*32 + lane] = ( W[2+3i][2l], W[2+3i][2l+1], W[3+3i][2l], W[3+3i][2l+1] )
    __shared__ float4 sW4[K1V * 32];
    __shared__ float  sWx[64], sWy[64], sWn[64], sB[64];
    __shared__ float4 pts[WARPS][K1V];   // (x, y, norm, (ii*32)_as_float)

    const int tid = threadIdx.x;

    // ---- stage derived weights (once per block) ----
    if (tid < 64) {
        const int u = tid;
        float wx = W[u];          // W[0][u]
        float wy = W[64 + u];     // W[1][u]
        float wn = 0.f;
        #pragma unroll
        for (int i = 0; i < K1V; i++) {
            wx -= W[(2 + 3 * i) * 64 + u];
            wy -= W[(3 + 3 * i) * 64 + u];
            wn += W[(4 + 3 * i) * 64 + u];
        }
        sWx[u] = wx; sWy[u] = wy; sWn[u] = wn; sB[u] = bvec[u];
    }
    {
        float* sW4F = (float*)sW4;
        #pragma unroll 1
        for (int t = tid; t < K1V * 128; t += 256) {
            const int i = t >> 7;            // point index
            const int l = (t >> 2) & 31;     // lane
            const int c = t & 3;             // component
            const int row = (c < 2 ? 2 : 3) + 3 * i;
            const int col = 2 * l + (c & 1);
            sW4F[t] = W[row * 64 + col];
        }
    }
    __syncthreads();

    const int lane = tid & 31, warp = tid >> 5;
    const unsigned g = blockIdx.x * WARPS + warp;   // neighborhood id in [0, BN)
    const unsigned b = g >> 14;                     // g / 16384
    const int* __restrict__ ip = nidx + (size_t)g * K1V;

    // ---- phase A: gather 17 points, norms; stash feats offset (ii*32) ----
    float x = 0.f, y = 0.f;
    if (lane < K1V) {
        const int ii = ip[lane];
        const float2 p = pc[(size_t)b * NPTS + ii];
        x = p.x; y = p.y;
        const float nrm = sqrtf(x * x + y * y);
        pts[warp][lane] = make_float4(x, y, nrm, __int_as_float(ii * 32));
    }
    __syncwarp();

    // ---- ggf: two-pass centered stats over 17 points (matches reference) ----
    float sx = x, sy = y;
    #pragma unroll
    for (int o = 16; o; o >>= 1) {
        sx += __shfl_xor_sync(0xffffffffu, sx, o);
        sy += __shfl_xor_sync(0xffffffffu, sy, o);
    }
    const float inv17 = 1.0f / 17.0f;
    const float mx = sx * inv17, my = sy * inv17;
    const float xc = (lane < K1V) ? (x - mx) : 0.f;
    const float yc = (lane < K1V) ? (y - my) : 0.f;
    float sxx = xc * xc, syy = yc * yc, sxy = xc * yc;
    #pragma unroll
    for (int o = 16; o; o >>= 1) {
        sxx += __shfl_xor_sync(0xffffffffu, sxx, o);
        syy += __shfl_xor_sync(0xffffffffu, syy, o);
        sxy += __shfl_xor_sync(0xffffffffu, sxy, o);
    }
    if (lane == 0) {
        const float vx = sxx * inv17, vy = syy * inv17, cov = sxy * inv17;
        const float m    = cov / (vx + 1e-8f);
        const float pear = cov / (sqrtf(vx * vy) + 1e-8f);
        __stcs(ggf + g, make_float2(m, 1.0f - pear));
    }

    // ---- phase B: shared projection S[u]; one LDS.128 (pt) + one LDS.128 (w) per i ----
    float acc0 = sB[2 * lane], acc1 = sB[2 * lane + 1];
    #pragma unroll
    for (int i = 0; i < K1V; i++) {
        const float4 pt = pts[warp][i];                  // LDS broadcast
        const float4 w  = sW4[i * 32 + lane];
        acc0 = fmaf(pt.x, w.x, acc0);
        acc1 = fmaf(pt.x, w.y, acc1);
        acc0 = fmaf(pt.y, w.z, acc0);
        acc1 = fmaf(pt.y, w.w, acc1);
    }
    const float wx0 = sWx[2 * lane], wx1 = sWx[2 * lane + 1];
    const float wy0 = sWy[2 * lane], wy1 = sWy[2 * lane + 1];
    const float wn0 = sWn[2 * lane], wn1 = sWn[2 * lane + 1];

    // ---- phase C: group-of-4 gather MLP; pts read exactly once per j ----
    float2* __restrict__ outBase = out + (size_t)g * (OUT_FLOATS_PER_G / 2) + lane;
    const float2* __restrict__ fb = feats + (size_t)b * NPTS * 32 + lane;

    #define CST(j, pt, fv) do {                                               \
        float r0 = fmaf((pt).z, wn0, fmaf((pt).y, wy0, fmaf((pt).x, wx0, acc0))); \
        float r1 = fmaf((pt).z, wn1, fmaf((pt).y, wy1, fmaf((pt).x, wx1, acc1))); \
        r0 = fmaxf(r0, 0.f); r1 = fmaxf(r1, 0.f);                             \
        float2* row = outBase + (j) * 64;                                     \
        __stcs(row, fv);                                                      \
        __stcs(row + 32, make_float2(r0, r1));                                \
    } while (0)

    #pragma unroll 1
    for (int j = 0; j < 16; j += 4) {
        // read the 4 pts ONCE into registers
        const float4 p0 = pts[warp][j];
        const float4 p1 = pts[warp][j + 1];
        const float4 p2 = pts[warp][j + 2];
        const float4 p3 = pts[warp][j + 3];
        // 4 independent gathers in flight
        const float2 q0 = fb[__float_as_int(p0.w)];
        const float2 q1 = fb[__float_as_int(p1.w)];
        const float2 q2 = fb[__float_as_int(p2.w)];
        const float2 q3 = fb[__float_as_int(p3.w)];
        CST(j + 0, p0, q0);
        CST(j + 1, p1, q1);
        CST(j + 2, p2, q2);
        CST(j + 3, p3, q3);
    }
    {
        const float4 p = pts[warp][16];
        const float2 q = fb[__float_as_int(p.w)];
        CST(16, p, q);
    }
    #undef CST
}

extern "C" void kernel_launch(void* const* d_in, const int* in_sizes, int n_in,
                              void* d_out, int out_size) {
    const float2* pc    = (const float2*)d_in[0];
    const float2* feats = (const float2*)d_in[1];
    const int*    nidx  = (const int*)d_in[2];
    const float*  W     = (const float*)d_in[3];
    const float*  bvec  = (const float*)d_in[4];

    float* out = (float*)d_out;
    // ggf tensor is concatenated after the main output
    float2* ggf = (float2*)(out + (size_t)BN * OUT_FLOATS_PER_G);

    locse_kernel<<<BN / WARPS, 256>>>(pc, feats, nidx, W, bvec,
                                      (float2*)out, ggf);
}